// round 8
// baseline (speedup 1.0000x reference)
#include <cuda_runtime.h>
#include <cuda_bf16.h>

// T=4096, B=512, n=32, deg=3. Sequential nonlinear RNN over T.
//
// R8 = R4 (best cell, rel_err 2.5e-3) with EXACTLY ONE change:
//   tanhf(poly)  ->  (float)tanh((double)poly)   [correctly-rounded-class]
//
// Evidence ladder (tanh accuracy is the only knob that matters):
//   rational approx (any substrate)  -> 6.2232e-2  (attractor, bit-stable)
//   libm tanhf (<=2 ulp)             -> 2.5e-3
//   => reference uses an ACCURATE tanh; go one rung more accurate.
//
// Kept from R4 (verbatim):
//   - one thread per batch element (16 blocks x 32 threads = 512 chains)
//   - all 32 states in scalar fp32 registers, fully unrolled
//   - plain CUDA expressions; nvcc free FMA contraction (R6 proved removing
//     contraction is wrong: 2.5e-3 -> 6.25e-2)
//   - natural-order sequential sum k=0..31

static constexpr int BATCH  = 512;
static constexpr int NSTATE = 32;
static constexpr int PF     = 8;   // current prefetch ring depth

__global__ void __launch_bounds__(32, 1)
rnn_firing_rate_r8(const float* __restrict__ currents,   // [T, B]
                   const float* __restrict__ a_vec,      // [n]
                   const float* __restrict__ b_vec,      // [n]
                   const float* __restrict__ ds,         // [n]
                   const float* __restrict__ poly_coeff, // [4]
                   const float* __restrict__ g_b,        // [1]
                   float* __restrict__ out,              // [T, B]
                   int T)
{
    const int batch = blockIdx.x * 32 + threadIdx.x;

    float av[NSTATE], bv[NSTATE], dec[NSTATE], v[NSTATE];
    #pragma unroll
    for (int k = 0; k < NSTATE; ++k) {
        av[k]  = a_vec[k];
        bv[k]  = b_vec[k];
        dec[k] = 1.0f - ds[k];
        v[k]   = 0.0f;
    }
    const float c0 = poly_coeff[0] * poly_coeff[0];
    const float c1 = poly_coeff[1] * poly_coeff[1];
    const float c2 = poly_coeff[2] * poly_coeff[2];
    const float c3 = poly_coeff[3] * poly_coeff[3];
    const float gbv = g_b[0];

    // current prefetch ring (keeps the LDG off the dependency chain)
    float cbuf[PF];
    #pragma unroll
    for (int i = 0; i < PF; ++i)
        cbuf[i] = (i < T) ? currents[i * BATCH + batch] : 0.0f;

    float fs = 0.0f;

    for (int t = 0; t < T; ++t) {
        const float cur = cbuf[t & (PF - 1)];
        const int tp = t + PF;
        if (tp < T) cbuf[t & (PF - 1)] = currents[tp * BATCH + batch];

        const float h = 1000.0f * fs;   // feedback uses PREVIOUS step's fs

        // v[k] = decay[k]*v[k] + cur*a[k] + h*b[k]; sum in natural order.
        // Plain expressions: nvcc contracts to FMA (matches reference).
        float s = 0.0f;
        #pragma unroll
        for (int k = 0; k < NSTATE; ++k) {
            v[k] = dec[k] * v[k] + cur * av[k] + h * bv[k];
            s += v[k];
        }

        // z = mean(v) - g_b ; poly = c0 + c1 z + c2 z^2 + c3 z^3
        const float z  = s * (1.0f / 32.0f) - gbv;
        const float z2 = z * z;
        const float z3 = z2 * z;
        const float poly = c0 + c1 * z + c2 * z2 + c3 * z3;

        // fs = relu(100 * tanh(poly))
        // THE ONE CHANGE: correctly-rounded-class tanh via fp64.
        const float th = (float)tanh((double)poly);
        fs = fmaxf(100.0f * th, 0.0f);

        out[t * BATCH + batch] = fs;
    }
}

extern "C" void kernel_launch(void* const* d_in, const int* in_sizes, int n_in,
                              void* d_out, int out_size)
{
    const float* currents   = (const float*)d_in[0];  // [T*B]
    const float* a_vec      = (const float*)d_in[1];  // [32]
    const float* b_vec      = (const float*)d_in[2];  // [32]
    const float* ds         = (const float*)d_in[3];  // [32]
    const float* poly_coeff = (const float*)d_in[4];  // [4]
    const float* g_b        = (const float*)d_in[5];  // [1]
    float* out = (float*)d_out;

    const int T = in_sizes[0] / BATCH;                // 4096

    rnn_firing_rate_r8<<<BATCH / 32, 32>>>(currents, a_vec, b_vec, ds,
                                           poly_coeff, g_b, out, T);
}

// round 9
// speedup vs baseline: 5.6248x; 5.6248x over previous
#include <cuda_runtime.h>
#include <cuda_bf16.h>

// T=4096, B=512, n=32, deg=3. Sequential nonlinear RNN over T.
//
// R9 = R8 (PASS, 1.64e-4, 4378us) with the fp64 tanh replaced by:
//   poly <= 0      -> fs = 0        (bit-identical to R8: relu clips)
//   poly >  9.2    -> fs = 100      (bit-identical: (float)tanh rounds to 1.0f)
//   poly in (0,9.2]-> double-float tanh on the FMA pipe (~2e-10 rel error,
//                     <1% 1-ulp mismatch vs correctly-rounded)
// plus a warp-uniform ballot skip of the expensive block.
//
// Recurrence / sum / poly code kept VERBATIM from R8 (nvcc contraction
// pattern is load-bearing: R6 proved removing it costs 25x in rel_err).

static constexpr int BATCH  = 512;
static constexpr int NSTATE = 32;
static constexpr int PF     = 8;   // current prefetch ring depth

// Accurate tanh for x in (0, 9.2] using double-float (f32-pair) arithmetic.
// tanh(x) = (E-1)/(E+1), E = e^{2x} = 2^k * e^r, r = 2x - k*ln2, |r|<=0.3466.
// All error-term computations use explicit fmaf so contraction cannot break
// the two_prod/two_sum identities.
__device__ __forceinline__ float tanh_df_pos(float x) {
    const float t  = 2.0f * x;                          // exact
    const float kf = rintf(t * 1.4426950408889634f);    // k in [0, 27]
    const int   ki = (int)kf;

    // r = t - k*ln2, exact double-float reduction
    const float L_h = 0.693147182464599609375f;          // float(ln2)
    const float L_l = -1.9046542996577634e-9f;           // ln2 - L_h
    float ph = kf * L_h;
    float pe = fmaf(kf, L_h, -ph);                       // exact product error
    float d  = t - ph;                                   // exact (Sterbenz / k=0)
    // two_sum(d, -pe)
    float s0  = d - pe;
    float bb0 = s0 - d;
    float er0 = (d - (s0 - bb0)) + (-pe - bb0);
    float rh = s0;
    float rl = er0 - kf * L_l;
    { float s = rh + rl; rl = rl - (s - rh); rh = s; }   // renorm

    // r^2 (df)
    float r2h = rh * rh;
    float r2l = fmaf(rh, rh, -r2h);
    r2l = fmaf(2.0f * rh, rl, r2l);
    { float s = r2h + r2l; r2l = r2l - (s - r2h); r2h = s; }

    // r^3 (df)
    float r3h = r2h * rh;
    float r3l = fmaf(r2h, rh, -r3h);
    r3l = fmaf(r2h, rl, fmaf(r2l, rh, r3l));

    // u = r^3 / 6 (df constant multiply)
    const float C6h = 0.166666671633720398f;             // float(1/6)
    const float C6l = -4.967053879312286e-9f;            // 1/6 - C6h
    float uh = r3h * C6h;
    float ul = fmaf(r3h, C6h, -uh);
    ul = fmaf(r3h, C6l, fmaf(r3l, C6h, ul));

    // tail: r^4 * (1/24 + r/120 + r^2/720 + r^3/5040 + r^4/40320 + r^5/362880)
    float R = fmaf(rh, 2.7557319224e-6f, 2.4801587302e-5f);
    R = fmaf(rh, R, 1.9841269841e-4f);
    R = fmaf(rh, R, 1.3888888889e-3f);
    R = fmaf(rh, R, 8.3333333333e-3f);
    R = fmaf(rh, R, 4.1666666667e-2f);
    const float r4    = r2h * r2h;
    const float tailv = r4 * R;

    // M = expm1(r) = r + r^2/2 + r^3/6 + tail   (df, magnitudes descending)
    float h2h = 0.5f * r2h, h2l = 0.5f * r2l;
    float mh = rh + h2h;
    float ml = (rh - mh) + h2h;                          // quick_two_sum (|rh|>=|h2h|)
    ml += rl + h2l;
    { float m2 = mh + uh; float m2l = (mh - m2) + uh; ml = ml + m2l + ul; mh = m2; }
    { float m3 = mh + tailv; float m3l = (mh - m3) + tailv; ml = ml + m3l; mh = m3; }
    { float s = mh + ml; ml = ml - (s - mh); mh = s; }

    // pk = 2^k ; pkM = pk*M (df, exact product error)
    const float pk = __int_as_float((ki + 127) << 23);
    float ah = pk * mh;
    float al = fmaf(pk, mh, -ah);
    al = fmaf(pk, ml, al);

    // N = (pk - 1) + pkM   [two_sum keeps 2^k-1 exact even at k>=25]
    float n1  = pk - 1.0f;
    float nb  = n1 - pk;
    float ne  = (pk - (n1 - nb)) + (-1.0f - nb);
    float nh  = n1 + ah;
    float tt1 = nh - n1;
    float nl  = (n1 - (nh - tt1)) + (ah - tt1);
    nl += ne + al;
    { float s = nh + nl; nl = nl - (s - nh); nh = s; }

    // D = (pk + 1) + pkM
    float d1  = pk + 1.0f;
    float db  = d1 - pk;
    float de  = (pk - (d1 - db)) + (1.0f - db);
    float dh  = d1 + ah;
    float tt2 = dh - d1;
    float dl  = (d1 - (dh - tt2)) + (ah - tt2);
    dl += de + al;
    { float s = dh + dl; dl = dl - (s - dh); dh = s; }

    // Q = N / D with one df correction step
    float rcp;
    asm("rcp.approx.f32 %0, %1;" : "=f"(rcp) : "f"(dh));
    float q0  = nh * rcp;
    float p   = q0 * dh;
    float pe2 = fmaf(q0, dh, -p);
    float rh2 = nh - p;                                  // Sterbenz (p ~ nh)
    float resid = rh2 - pe2 + (nl - q0 * dl);
    return fmaf(resid, rcp, q0);
}

__global__ void __launch_bounds__(32, 1)
rnn_firing_rate_r9(const float* __restrict__ currents,   // [T, B]
                   const float* __restrict__ a_vec,      // [n]
                   const float* __restrict__ b_vec,      // [n]
                   const float* __restrict__ ds,         // [n]
                   const float* __restrict__ poly_coeff, // [4]
                   const float* __restrict__ g_b,        // [1]
                   float* __restrict__ out,              // [T, B]
                   int T)
{
    const int batch = blockIdx.x * 32 + threadIdx.x;

    float av[NSTATE], bv[NSTATE], dec[NSTATE], v[NSTATE];
    #pragma unroll
    for (int k = 0; k < NSTATE; ++k) {
        av[k]  = a_vec[k];
        bv[k]  = b_vec[k];
        dec[k] = 1.0f - ds[k];
        v[k]   = 0.0f;
    }
    const float c0 = poly_coeff[0] * poly_coeff[0];
    const float c1 = poly_coeff[1] * poly_coeff[1];
    const float c2 = poly_coeff[2] * poly_coeff[2];
    const float c3 = poly_coeff[3] * poly_coeff[3];
    const float gbv = g_b[0];

    // current prefetch ring (keeps the LDG off the dependency chain)
    float cbuf[PF];
    #pragma unroll
    for (int i = 0; i < PF; ++i)
        cbuf[i] = (i < T) ? currents[i * BATCH + batch] : 0.0f;

    float fs = 0.0f;

    for (int t = 0; t < T; ++t) {
        const float cur = cbuf[t & (PF - 1)];
        const int tp = t + PF;
        if (tp < T) cbuf[t & (PF - 1)] = currents[tp * BATCH + batch];

        const float h = 1000.0f * fs;   // feedback uses PREVIOUS step's fs

        // v[k] = decay[k]*v[k] + cur*a[k] + h*b[k]; sum in natural order.
        // VERBATIM from R8: nvcc contraction here matches the reference.
        float s = 0.0f;
        #pragma unroll
        for (int k = 0; k < NSTATE; ++k) {
            v[k] = dec[k] * v[k] + cur * av[k] + h * bv[k];
            s += v[k];
        }

        // z = mean(v) - g_b ; poly = c0 + c1 z + c2 z^2 + c3 z^3 (verbatim R8)
        const float z  = s * (1.0f / 32.0f) - gbv;
        const float z2 = z * z;
        const float z3 = z2 * z;
        const float poly = c0 + c1 * z + c2 * z2 + c3 * z3;

        // fs = relu(100 * tanh(poly)):
        //   poly <= 0   -> 0      (bit-identical to R8)
        //   poly >  9.2 -> 100    (bit-identical: tanh rounds to 1.0f)
        //   else        -> df tanh (correctly-rounded-class, FMA pipe)
        const bool mid = (poly > 0.0f) && (poly <= 9.2f);
        float fs_mid = 0.0f;
        if (__ballot_sync(0xFFFFFFFFu, mid)) {
            const float th = tanh_df_pos(poly);
            fs_mid = fmaxf(100.0f * th, 0.0f);
        }
        fs = (poly <= 0.0f) ? 0.0f : ((poly > 9.2f) ? 100.0f : fs_mid);

        out[t * BATCH + batch] = fs;
    }
}

extern "C" void kernel_launch(void* const* d_in, const int* in_sizes, int n_in,
                              void* d_out, int out_size)
{
    const float* currents   = (const float*)d_in[0];  // [T*B]
    const float* a_vec      = (const float*)d_in[1];  // [32]
    const float* b_vec      = (const float*)d_in[2];  // [32]
    const float* ds         = (const float*)d_in[3];  // [32]
    const float* poly_coeff = (const float*)d_in[4];  // [4]
    const float* g_b        = (const float*)d_in[5];  // [1]
    float* out = (float*)d_out;

    const int T = in_sizes[0] / BATCH;                // 4096

    rnn_firing_rate_r9<<<BATCH / 32, 32>>>(currents, a_vec, b_vec, ds,
                                           poly_coeff, g_b, out, T);
}

// round 10
// speedup vs baseline: 7.9334x; 1.4104x over previous
#include <cuda_runtime.h>
#include <cuda_bf16.h>

// T=4096, B=512, n=32, deg=3. Sequential nonlinear RNN over T.
//
// R10 = R9 (PASS 778us, rel_err 1.637e-4) with:
//   1. leaner double-float tanh (shorter spine, fma-based div correction;
//      abs err <= ~5e-9, inside the ~1e-8 budget established by the ladder)
//   2. t-loop unrolled x8 so the current-prefetch ring has static indices
//      (registers, no local-memory LDL/STL)
//   3. output via running pointer (alu-pipe IADD, off the fma pipe)
// Recurrence / sum / poly / select expressions VERBATIM from R9 — that
// contraction pattern is matched to the reference (R6: removing it = 25x).

static constexpr int BATCH  = 512;
static constexpr int NSTATE = 32;
static constexpr int PF     = 8;   // ring depth == unroll factor

// Lean double-float tanh for x in (0, 9.2].
// tanh(x) = N/D, N = (2^k - 1) + 2^k*M, D = (2^k + 1) + 2^k*M,
// M = expm1(r), r = 2x - k*ln2, |r| <= 0.3466.
// df only on: r, r^2/2, N/D sums, final division correction.
__device__ __forceinline__ float tanh_df_lean(float x) {
    const float t  = 2.0f * x;                           // exact
    const float kf = rintf(t * 1.4426950408889634f);     // k in [0,27]
    const int   ki = (int)kf;

    // r = t - kf*ln2 (df): d = t - kf*L_h exact (Sterbenz / k=0)
    const float L_h = 0.693147182464599609375f;
    const float L_l = -1.9046542996577634e-9f;
    const float ph = kf * L_h;
    const float pe = fmaf(kf, L_h, -ph);                 // exact product error
    const float d  = t - ph;                             // exact
    // two_sum(d, -pe)
    const float rh = d - pe;
    const float bb = rh - d;
    const float er = (d - (rh - bb)) + (-pe - bb);
    const float rl = er - kf * L_l;

    // r^2 (df): r2l includes cross term 2*rh*rl
    const float r2h = rh * rh;
    float r2l = fmaf(rh, rh, -r2h);
    r2l = fmaf(2.0f * rh, rl, r2l);

    // cubic-and-up tail in plain f32 (magnitude <= 7e-3, noise ~1e-9):
    // r^3*(1/6 + r/24 + r^2/120 + r^3/720 + r^4/5040 + r^5/40320)
    float C = fmaf(rh, 2.4801587302e-5f, 1.9841269841e-4f);
    C = fmaf(rh, C, 1.3888888889e-3f);
    C = fmaf(rh, C, 8.3333333333e-3f);
    C = fmaf(rh, C, 4.1666666667e-2f);
    C = fmaf(rh, C, 1.6666666667e-1f);
    const float cub = (r2h * rh) * C;

    // M = expm1(r) = (rh + r2h/2) [quick_two_sum, |rh| >= r^2/2] + small terms
    const float q  = 0.5f * r2h;
    float mh = rh + q;
    float ml = (rh - mh) + q;                            // exact low word
    ml = ml + (cub + (rl + 0.5f * r2l));
    { const float s = mh + ml; ml = ml - (s - mh); mh = s; }  // renorm

    // A = 2^k * M (df)
    const float pk = __int_as_float((ki + 127) << 23);
    const float ah = pk * mh;
    const float al = fmaf(pk, ml, fmaf(pk, mh, -ah));

    // N = (pk - 1) + A   (two_sum keeps pk-1 exact even at k >= 25)
    const float n1 = pk - 1.0f;
    const float nd = n1 - pk;
    const float ne = (pk - (n1 - nd)) + (-1.0f - nd);
    const float nh = n1 + ah;
    const float tb1 = nh - n1;
    const float nl = ((n1 - (nh - tb1)) + (ah - tb1)) + ne + al;

    // D = (pk + 1) + A
    const float d1 = pk + 1.0f;
    const float dd = d1 - pk;
    const float de = (pk - (d1 - dd)) + (1.0f - dd);
    const float dh = d1 + ah;
    const float tb2 = dh - d1;
    const float dl = ((d1 - (dh - tb2)) + (ah - tb2)) + de + al;

    // q = N/D with one fma-based df correction
    float rcp;
    asm("rcp.approx.f32 %0, %1;" : "=f"(rcp) : "f"(dh));
    const float q0 = nh * rcp;
    const float e1 = fmaf(-q0, dh, nh);                  // exact-ish residual
    const float resid = e1 + fmaf(-q0, dl, nl);
    return fmaf(resid, rcp, q0);
}

__global__ void __launch_bounds__(32, 1)
rnn_firing_rate_r10(const float* __restrict__ currents,   // [T, B]
                    const float* __restrict__ a_vec,      // [n]
                    const float* __restrict__ b_vec,      // [n]
                    const float* __restrict__ ds,         // [n]
                    const float* __restrict__ poly_coeff, // [4]
                    const float* __restrict__ g_b,        // [1]
                    float* __restrict__ out,              // [T, B]
                    int T)
{
    const int batch = blockIdx.x * 32 + threadIdx.x;

    float av[NSTATE], bv[NSTATE], dec[NSTATE], v[NSTATE];
    #pragma unroll
    for (int k = 0; k < NSTATE; ++k) {
        av[k]  = a_vec[k];
        bv[k]  = b_vec[k];
        dec[k] = 1.0f - ds[k];
        v[k]   = 0.0f;
    }
    const float c0 = poly_coeff[0] * poly_coeff[0];
    const float c1 = poly_coeff[1] * poly_coeff[1];
    const float c2 = poly_coeff[2] * poly_coeff[2];
    const float c3 = poly_coeff[3] * poly_coeff[3];
    const float gbv = g_b[0];

    // current prefetch ring — static indices after unroll => registers
    float cbuf[PF];
    #pragma unroll
    for (int i = 0; i < PF; ++i)
        cbuf[i] = (i < T) ? currents[i * BATCH + batch] : 0.0f;

    const float* cptr = currents + (size_t)PF * BATCH + batch; // next fetch
    float*       optr = out + batch;

    float fs = 0.0f;

    for (int tblk = 0; tblk < T; tblk += PF) {
        #pragma unroll
        for (int u = 0; u < PF; ++u) {
            const int t = tblk + u;
            const float cur = cbuf[u];
            if (t + PF < T) cbuf[u] = cptr[u * BATCH];

            const float h = 1000.0f * fs;   // feedback from PREVIOUS step

            // v[k] = decay[k]*v[k] + cur*a[k] + h*b[k]; natural-order sum.
            // VERBATIM from R9: nvcc contraction matches the reference.
            float s = 0.0f;
            #pragma unroll
            for (int k = 0; k < NSTATE; ++k) {
                v[k] = dec[k] * v[k] + cur * av[k] + h * bv[k];
                s += v[k];
            }

            // z = mean(v) - g_b ; poly = c0 + c1 z + c2 z^2 + c3 z^3
            const float z  = s * (1.0f / 32.0f) - gbv;
            const float z2 = z * z;
            const float z3 = z2 * z;
            const float poly = c0 + c1 * z + c2 * z2 + c3 * z3;

            // fs = relu(100 * tanh(poly)):
            //   poly <= 0   -> 0    ; poly > 9.2 -> 100 (tanh rounds to 1.0f)
            //   else        -> lean df tanh
            const bool mid = (poly > 0.0f) && (poly <= 9.2f);
            float fs_mid = 0.0f;
            if (__ballot_sync(0xFFFFFFFFu, mid)) {
                const float th = tanh_df_lean(poly);
                fs_mid = fmaxf(100.0f * th, 0.0f);
            }
            fs = (poly <= 0.0f) ? 0.0f : ((poly > 9.2f) ? 100.0f : fs_mid);

            *optr = fs;
            optr += BATCH;
        }
        cptr += PF * BATCH;
    }
}

extern "C" void kernel_launch(void* const* d_in, const int* in_sizes, int n_in,
                              void* d_out, int out_size)
{
    const float* currents   = (const float*)d_in[0];  // [T*B]
    const float* a_vec      = (const float*)d_in[1];  // [32]
    const float* b_vec      = (const float*)d_in[2];  // [32]
    const float* ds         = (const float*)d_in[3];  // [32]
    const float* poly_coeff = (const float*)d_in[4];  // [4]
    const float* g_b        = (const float*)d_in[5];  // [1]
    float* out = (float*)d_out;

    const int T = in_sizes[0] / BATCH;                // 4096

    rnn_firing_rate_r10<<<BATCH / 32, 32>>>(currents, a_vec, b_vec, ds,
                                            poly_coeff, g_b, out, T);
}